// round 6
// baseline (speedup 1.0000x reference)
#include <cuda_runtime.h>
#include <cstdint>
#include <math.h>

#define TT   512
#define HD   2048
#define EE   32
#define KTOP 4
#define FF   1024
#define NZ   16
#define ZHD  512

__device__ float g_zh[TT * ZHD];
__device__ float g_act[(size_t)EE * TT * FF];
__device__ int   g_cnt[EE];
__device__ int   g_tok[EE * TT];
__device__ float g_wgt[EE * TT];

__device__ __forceinline__ unsigned f2tf(float f) {
    unsigned u;
    asm("cvt.rna.tf32.f32 %0, %1;" : "=r"(u) : "f"(f));
    return u;
}

__device__ __forceinline__ void mma_tf32(float& d0, float& d1, float& d2, float& d3,
                                         unsigned a0, unsigned a1, unsigned a2, unsigned a3,
                                         unsigned b0, unsigned b1) {
    asm volatile("mma.sync.aligned.m16n8k8.row.col.f32.tf32.tf32.f32 "
                 "{%0,%1,%2,%3}, {%4,%5,%6,%7}, {%8,%9}, {%0,%1,%2,%3};"
                 : "+f"(d0), "+f"(d1), "+f"(d2), "+f"(d3)
                 : "r"(a0), "r"(a1), "r"(a2), "r"(a3), "r"(b0), "r"(b1));
}

// ---------------------------------------------------------------------------
// K0: zero output + expert counters
// ---------------------------------------------------------------------------
__global__ void k_zero(float* __restrict__ out) {
    int i = blockIdx.x * blockDim.x + threadIdx.x;
    if (i < TT * HD) out[i] = 0.0f;
    if (i < EE) g_cnt[i] = 0;
}

// ---------------------------------------------------------------------------
// K1: zh = silu(x @ z_w1^T + b1). M=128 tokens, N=64, K=HD. (unchanged)
// ---------------------------------------------------------------------------
__global__ __launch_bounds__(256, 2) void k_zh(const float* __restrict__ x,
                                               const float* __restrict__ w1,
                                               const float* __restrict__ b1) {
    int m0 = blockIdx.y * 128, n0 = blockIdx.x * 64;
    __shared__ unsigned As[128][20];
    __shared__ unsigned Bs[64][20];
    int tid = threadIdx.x, lane = tid & 31, warp = tid >> 5;
    int wm = warp >> 1, wn = warp & 1;
    int lq = lane >> 2, lr = lane & 3;
    int bn = tid >> 2, bkc = (tid & 3) * 4;

    float acc[2][4][4] = {};
    float4 rA[2], rB;
#pragma unroll
    for (int p = 0; p < 2; p++) {
        int s = tid + p * 256, r = s >> 2, kc = (s & 3) * 4;
        rA[p] = *(const float4*)&x[(size_t)(m0 + r) * HD + kc];
    }
    rB = *(const float4*)&w1[(size_t)(n0 + bn) * HD + bkc];
#pragma unroll
    for (int p = 0; p < 2; p++) {
        int s = tid + p * 256, r = s >> 2, kc = (s & 3) * 4;
        uint4 w = {f2tf(rA[p].x), f2tf(rA[p].y), f2tf(rA[p].z), f2tf(rA[p].w)};
        *(uint4*)&As[r][kc] = w;
    }
    {
        uint4 w = {f2tf(rB.x), f2tf(rB.y), f2tf(rB.z), f2tf(rB.w)};
        *(uint4*)&Bs[bn][bkc] = w;
    }
    __syncthreads();

    for (int k0 = 0; k0 < HD; k0 += 16) {
        bool more = (k0 + 16) < HD;
        if (more) {
            int kn = k0 + 16;
#pragma unroll
            for (int p = 0; p < 2; p++) {
                int s = tid + p * 256, r = s >> 2, kc = (s & 3) * 4;
                rA[p] = *(const float4*)&x[(size_t)(m0 + r) * HD + kn + kc];
            }
            rB = *(const float4*)&w1[(size_t)(n0 + bn) * HD + kn + bkc];
        }
#pragma unroll
        for (int k8 = 0; k8 < 2; k8++) {
            int kb = k8 * 8 + lr;
            unsigned a[2][4];
#pragma unroll
            for (int mi = 0; mi < 2; mi++) {
                int r = wm * 32 + mi * 16 + lq;
                a[mi][0] = As[r][kb];     a[mi][1] = As[r + 8][kb];
                a[mi][2] = As[r][kb + 4]; a[mi][3] = As[r + 8][kb + 4];
            }
#pragma unroll
            for (int ni = 0; ni < 4; ni++) {
                int nn = wn * 32 + ni * 8 + lq;
                unsigned b0 = Bs[nn][kb], b1r = Bs[nn][kb + 4];
#pragma unroll
                for (int mi = 0; mi < 2; mi++)
                    mma_tf32(acc[mi][ni][0], acc[mi][ni][1], acc[mi][ni][2], acc[mi][ni][3],
                             a[mi][0], a[mi][1], a[mi][2], a[mi][3], b0, b1r);
            }
        }
        __syncthreads();
        if (more) {
#pragma unroll
            for (int p = 0; p < 2; p++) {
                int s = tid + p * 256, r = s >> 2, kc = (s & 3) * 4;
                uint4 w = {f2tf(rA[p].x), f2tf(rA[p].y), f2tf(rA[p].z), f2tf(rA[p].w)};
                *(uint4*)&As[r][kc] = w;
            }
            uint4 w = {f2tf(rB.x), f2tf(rB.y), f2tf(rB.z), f2tf(rB.w)};
            *(uint4*)&Bs[bn][bkc] = w;
            __syncthreads();
        }
    }
#pragma unroll
    for (int mi = 0; mi < 2; mi++)
#pragma unroll
        for (int half = 0; half < 2; half++) {
            int r = m0 + wm * 32 + mi * 16 + lq + half * 8;
#pragma unroll
            for (int ni = 0; ni < 4; ni++)
#pragma unroll
                for (int c = 0; c < 2; c++) {
                    int col = n0 + wn * 32 + ni * 8 + lr * 2 + c;
                    float v = acc[mi][ni][half * 2 + c] + b1[col];
                    g_zh[(size_t)r * ZHD + col] = v / (1.0f + expf(-v));
                }
        }
}

// ---------------------------------------------------------------------------
// K2: per-token router (unchanged)
// ---------------------------------------------------------------------------
__global__ __launch_bounds__(128) void k_router(const float* __restrict__ x,
                                                const float* __restrict__ u,
                                                const float* __restrict__ gate_w,
                                                const float* __restrict__ z_w2,
                                                const float* __restrict__ z_b2,
                                                const float* __restrict__ Umat) {
    int t = blockIdx.x;
    __shared__ float xs[HD];
    __shared__ float rl[EE];
    __shared__ float zl[NZ];
    int tid = threadIdx.x, lane = tid & 31, warp = tid >> 5;

    for (int i = tid; i < HD; i += 128) xs[i] = x[t * HD + i];
    __syncthreads();

    for (int e = warp; e < EE; e += 4) {
        float s = 0.0f;
        const float* gw = gate_w + e * HD;
        for (int i = lane; i < HD; i += 32) s += xs[i] * gw[i];
#pragma unroll
        for (int o = 16; o; o >>= 1) s += __shfl_down_sync(0xffffffffu, s, o);
        if (lane == 0) rl[e] = s;
    }
    for (int j = warp; j < NZ; j += 4) {
        float s = 0.0f;
        const float* zw = z_w2 + j * ZHD;
        const float* zh = g_zh + t * ZHD;
        for (int i = lane; i < ZHD; i += 32) s += zh[i] * zw[i];
#pragma unroll
        for (int o = 16; o; o >>= 1) s += __shfl_down_sync(0xffffffffu, s, o);
        if (lane == 0) zl[j] = s + z_b2[j];
    }
    __syncthreads();

    if (tid == 0) {
        int zi = 0;
        float best = -1e30f;
        for (int j = 0; j < NZ; j++) {
            float g = -logf(-logf(u[t * NZ + j]));
            float v = zl[j] + g;
            if (v > best) { best = v; zi = j; }
        }
        float lg[EE];
        float mx = -1e30f;
        for (int e = 0; e < EE; e++) {
            lg[e] = rl[e] + Umat[zi * EE + e];
            mx = fmaxf(mx, lg[e]);
        }
        float sum = 0.0f;
        for (int e = 0; e < EE; e++) { lg[e] = expf(lg[e] - mx); sum += lg[e]; }
        float inv = 1.0f / sum;
        for (int k = 0; k < KTOP; k++) {
            int be = 0;
            float bv = -1.0f;
            for (int e = 0; e < EE; e++)
                if (lg[e] > bv) { bv = lg[e]; be = e; }
            float w = bv * inv;
            lg[be] = -1.0f;
            int pos = atomicAdd(&g_cnt[be], 1);
            g_tok[be * TT + pos] = t;
            g_wgt[be * TT + pos] = w;
        }
    }
}

// ---------------------------------------------------------------------------
// K3: gate/up GEMMs + SwiGLU*comb -> g_act. tf32 mma.
// CTA: M=64 gathered tokens x N=128 f-cols of BOTH Wg and Wu. K=HD.
// 8 warps: wm in {0,1} (32 rows), wn in {0..3} (32 cols), each warp does
// m32 x n32 on both matrices (16 mma per k8). grid (FF/128, EE).
// ---------------------------------------------------------------------------
__global__ __launch_bounds__(256, 2) void k_gateup(const float* __restrict__ x,
                                                   const float* __restrict__ Wg,
                                                   const float* __restrict__ Wu) {
    int e = blockIdx.y;
    int n = g_cnt[e];
    if (n == 0) return;
    int f0 = blockIdx.x * 128;
    __shared__ unsigned As[64][20];
    __shared__ unsigned Bg[128][20];
    __shared__ unsigned Bu[128][20];
    __shared__ int toks[64];
    int tid = threadIdx.x, lane = tid & 31, warp = tid >> 5;
    int wm = warp >> 2, wn = warp & 3;
    int lq = lane >> 2, lr = lane & 3;
    const float* wg = Wg + (size_t)e * HD * FF + f0;
    const float* wu = Wu + (size_t)e * HD * FF + f0;
    // A staging: 64 rows x 16 k = 256 float4, 1 per thread
    int ar = tid >> 2, akc = (tid & 3) * 4;
    // B staging: 16 kk x 128 f = 512 float4 per matrix, 2 per thread
    int bkk = tid >> 4;           // 0..15

    for (int s0 = 0; s0 < n; s0 += 64) {
        __syncthreads();
        int nt = min(64, n - s0);
        if (tid < 64) toks[tid] = (tid < nt) ? g_tok[e * TT + s0 + tid] : 0;
        __syncthreads();

        float acg[4][4] = {}, acu[4][4] = {};   // [ni][frag] for gate/up (mi folded: m32 = 2x16)
        float acg1[4][4] = {}, acu1[4][4] = {};
        float4 rA, rG[2], rU[2];

        // prologue k0 = 0
        rA = (ar < nt) ? *(const float4*)&x[(size_t)toks[ar] * HD + akc]
                       : make_float4(0.f, 0.f, 0.f, 0.f);
#pragma unroll
        for (int p = 0; p < 2; p++) {
            int fb = ((tid & 15) + p * 16) * 4;
            rG[p] = *(const float4*)&wg[(size_t)bkk * FF + fb];
            rU[p] = *(const float4*)&wu[(size_t)bkk * FF + fb];
        }
        {
            uint4 w = {f2tf(rA.x), f2tf(rA.y), f2tf(rA.z), f2tf(rA.w)};
            *(uint4*)&As[ar][akc] = w;
#pragma unroll
            for (int p = 0; p < 2; p++) {
                int fb = ((tid & 15) + p * 16) * 4;
                Bg[fb + 0][bkk] = f2tf(rG[p].x); Bg[fb + 1][bkk] = f2tf(rG[p].y);
                Bg[fb + 2][bkk] = f2tf(rG[p].z); Bg[fb + 3][bkk] = f2tf(rG[p].w);
                Bu[fb + 0][bkk] = f2tf(rU[p].x); Bu[fb + 1][bkk] = f2tf(rU[p].y);
                Bu[fb + 2][bkk] = f2tf(rU[p].z); Bu[fb + 3][bkk] = f2tf(rU[p].w);
            }
        }
        __syncthreads();

        for (int k0 = 0; k0 < HD; k0 += 16) {
            bool more = (k0 + 16) < HD;
            if (more) {
                int kn = k0 + 16;
                rA = (ar < nt) ? *(const float4*)&x[(size_t)toks[ar] * HD + kn + akc]
                               : make_float4(0.f, 0.f, 0.f, 0.f);
#pragma unroll
                for (int p = 0; p < 2; p++) {
                    int fb = ((tid & 15) + p * 16) * 4;
                    rG[p] = *(const float4*)&wg[(size_t)(kn + bkk) * FF + fb];
                    rU[p] = *(const float4*)&wu[(size_t)(kn + bkk) * FF + fb];
                }
            }
#pragma unroll
            for (int k8 = 0; k8 < 2; k8++) {
                int kb = k8 * 8 + lr;
                unsigned a[2][4];
#pragma unroll
                for (int mi = 0; mi < 2; mi++) {
                    int r = wm * 32 + mi * 16 + lq;
                    a[mi][0] = As[r][kb];     a[mi][1] = As[r + 8][kb];
                    a[mi][2] = As[r][kb + 4]; a[mi][3] = As[r + 8][kb + 4];
                }
#pragma unroll
                for (int ni = 0; ni < 4; ni++) {
                    int nn = wn * 32 + ni * 8 + lq;
                    unsigned g0 = Bg[nn][kb], g1 = Bg[nn][kb + 4];
                    unsigned u0 = Bu[nn][kb], u1 = Bu[nn][kb + 4];
                    mma_tf32(acg[ni][0], acg[ni][1], acg[ni][2], acg[ni][3],
                             a[0][0], a[0][1], a[0][2], a[0][3], g0, g1);
                    mma_tf32(acu[ni][0], acu[ni][1], acu[ni][2], acu[ni][3],
                             a[0][0], a[0][1], a[0][2], a[0][3], u0, u1);
                    mma_tf32(acg1[ni][0], acg1[ni][1], acg1[ni][2], acg1[ni][3],
                             a[1][0], a[1][1], a[1][2], a[1][3], g0, g1);
                    mma_tf32(acu1[ni][0], acu1[ni][1], acu1[ni][2], acu1[ni][3],
                             a[1][0], a[1][1], a[1][2], a[1][3], u0, u1);
                }
            }
            __syncthreads();
            if (more) {
                uint4 w = {f2tf(rA.x), f2tf(rA.y), f2tf(rA.z), f2tf(rA.w)};
                *(uint4*)&As[ar][akc] = w;
#pragma unroll
                for (int p = 0; p < 2; p++) {
                    int fb = ((tid & 15) + p * 16) * 4;
                    Bg[fb + 0][bkk] = f2tf(rG[p].x); Bg[fb + 1][bkk] = f2tf(rG[p].y);
                    Bg[fb + 2][bkk] = f2tf(rG[p].z); Bg[fb + 3][bkk] = f2tf(rG[p].w);
                    Bu[fb + 0][bkk] = f2tf(rU[p].x); Bu[fb + 1][bkk] = f2tf(rU[p].y);
                    Bu[fb + 2][bkk] = f2tf(rU[p].z); Bu[fb + 3][bkk] = f2tf(rU[p].w);
                }
                __syncthreads();
            }
        }
        // epilogue: SwiGLU * comb -> g_act
#pragma unroll
        for (int mi = 0; mi < 2; mi++)
#pragma unroll
            for (int half = 0; half < 2; half++) {
                int r = wm * 32 + mi * 16 + lq + half * 8;
                if (r < nt) {
                    float wc = g_wgt[e * TT + s0 + r];
                    size_t base = ((size_t)e * TT + s0 + r) * FF + f0 + wn * 32;
#pragma unroll
                    for (int ni = 0; ni < 4; ni++)
#pragma unroll
                        for (int c = 0; c < 2; c++) {
                            float gv = mi ? acg1[ni][half * 2 + c] : acg[ni][half * 2 + c];
                            float uv = mi ? acu1[ni][half * 2 + c] : acu[ni][half * 2 + c];
                            float act = gv / (1.0f + expf(-gv)) * uv * wc;
                            g_act[base + ni * 8 + lr * 2 + c] = act;
                        }
                }
            }
    }
}

// ---------------------------------------------------------------------------
// K4: down projection. CTA: M=64 tokens x N=128 h-cols, K=FF. tf32 mma.
// 8 warps: wm {0,1} x wn {0..3}, warp m32 x n32. grid (HD/128, EE).
// ---------------------------------------------------------------------------
__global__ __launch_bounds__(256, 2) void k_down(const float* __restrict__ Wd,
                                                 float* __restrict__ out) {
    int e = blockIdx.y;
    int n = g_cnt[e];
    if (n == 0) return;
    int h0 = blockIdx.x * 128;
    __shared__ unsigned As[64][20];
    __shared__ unsigned Bs[128][20];
    __shared__ int toks[64];
    int tid = threadIdx.x, lane = tid & 31, warp = tid >> 5;
    int wm = warp >> 2, wn = warp & 3;
    int lq = lane >> 2, lr = lane & 3;
    const float* wd = Wd + (size_t)e * FF * HD + h0;
    int ar = tid >> 2, akc = (tid & 3) * 4;
    int bkk = tid >> 4;

    for (int s0 = 0; s0 < n; s0 += 64) {
        __syncthreads();
        int nt = min(64, n - s0);
        if (tid < 64) toks[tid] = (tid < nt) ? g_tok[e * TT + s0 + tid] : 0;
        __syncthreads();

        float acc0[4][4] = {}, acc1[4][4] = {};
        float4 rA, rB[2];

        rA = (ar < nt) ? *(const float4*)&g_act[((size_t)e * TT + s0 + ar) * FF + akc]
                       : make_float4(0.f, 0.f, 0.f, 0.f);
#pragma unroll
        for (int p = 0; p < 2; p++) {
            int hb = ((tid & 15) + p * 16) * 4;
            rB[p] = *(const float4*)&wd[(size_t)bkk * HD + hb];
        }
        {
            uint4 w = {f2tf(rA.x), f2tf(rA.y), f2tf(rA.z), f2tf(rA.w)};
            *(uint4*)&As[ar][akc] = w;
#pragma unroll
            for (int p = 0; p < 2; p++) {
                int hb = ((tid & 15) + p * 16) * 4;
                Bs[hb + 0][bkk] = f2tf(rB[p].x); Bs[hb + 1][bkk] = f2tf(rB[p].y);
                Bs[hb + 2][bkk] = f2tf(rB[p].z); Bs[hb + 3][bkk] = f2tf(rB[p].w);
            }
        }
        __syncthreads();

        for (int k0 = 0; k0 < FF; k0 += 16) {
            bool more = (k0 + 16) < FF;
            if (more) {
                int kn = k0 + 16;
                rA = (ar < nt) ? *(const float4*)&g_act[((size_t)e * TT + s0 + ar) * FF + kn + akc]
                               : make_float4(0.f, 0.f, 0.f, 0.f);
#pragma unroll
                for (int p = 0; p < 2; p++) {
                    int hb = ((tid & 15) + p * 16) * 4;
                    rB[p] = *(const float4*)&wd[(size_t)(kn + bkk) * HD + hb];
                }
            }
#pragma unroll
            for (int k8 = 0; k8 < 2; k8++) {
                int kb = k8 * 8 + lr;
                unsigned a[2][4];
#pragma unroll
                for (int mi = 0; mi < 2; mi++) {
                    int r = wm * 32 + mi * 16 + lq;
                    a[mi][0] = As[r][kb];     a[mi][1] = As[r + 8][kb];
                    a[mi][2] = As[r][kb + 4]; a[mi][3] = As[r + 8][kb + 4];
                }
#pragma unroll
                for (int ni = 0; ni < 4; ni++) {
                    int nn = wn * 32 + ni * 8 + lq;
                    unsigned b0 = Bs[nn][kb], b1r = Bs[nn][kb + 4];
                    mma_tf32(acc0[ni][0], acc0[ni][1], acc0[ni][2], acc0[ni][3],
                             a[0][0], a[0][1], a[0][2], a[0][3], b0, b1r);
                    mma_tf32(acc1[ni][0], acc1[ni][1], acc1[ni][2], acc1[ni][3],
                             a[1][0], a[1][1], a[1][2], a[1][3], b0, b1r);
                }
            }
            __syncthreads();
            if (more) {
                uint4 w = {f2tf(rA.x), f2tf(rA.y), f2tf(rA.z), f2tf(rA.w)};
                *(uint4*)&As[ar][akc] = w;
#pragma unroll
                for (int p = 0; p < 2; p++) {
                    int hb = ((tid & 15) + p * 16) * 4;
                    Bs[hb + 0][bkk] = f2tf(rB[p].x); Bs[hb + 1][bkk] = f2tf(rB[p].y);
                    Bs[hb + 2][bkk] = f2tf(rB[p].z); Bs[hb + 3][bkk] = f2tf(rB[p].w);
                }
                __syncthreads();
            }
        }
        // epilogue: atomicAdd into out
#pragma unroll
        for (int mi = 0; mi < 2; mi++)
#pragma unroll
            for (int half = 0; half < 2; half++) {
                int r = wm * 32 + mi * 16 + lq + half * 8;
                if (r < nt) {
                    int t = toks[r];
                    size_t base = (size_t)t * HD + h0 + wn * 32;
#pragma unroll
                    for (int ni = 0; ni < 4; ni++)
#pragma unroll
                        for (int c = 0; c < 2; c++) {
                            float v = mi ? acc1[ni][half * 2 + c] : acc0[ni][half * 2 + c];
                            atomicAdd(&out[base + ni * 8 + lr * 2 + c], v);
                        }
                }
            }
    }
}

// ---------------------------------------------------------------------------
// launch
// ---------------------------------------------------------------------------
extern "C" void kernel_launch(void* const* d_in, const int* in_sizes, int n_in,
                              void* d_out, int out_size) {
    const float* x      = (const float*)d_in[0];
    const float* u      = (const float*)d_in[1];
    const float* gate_w = (const float*)d_in[2];
    const float* z_w1   = (const float*)d_in[3];
    const float* z_b1   = (const float*)d_in[4];
    const float* z_w2   = (const float*)d_in[5];
    const float* z_b2   = (const float*)d_in[6];
    const float* Umat   = (const float*)d_in[7];
    const float* Wg     = (const float*)d_in[8];
    const float* Wu     = (const float*)d_in[9];
    const float* Wd     = (const float*)d_in[10];
    float* out = (float*)d_out;

    k_zero<<<(TT * HD + 255) / 256, 256>>>(out);
    k_zh<<<dim3(ZHD / 64, TT / 128), 256>>>(x, z_w1, z_b1);
    k_router<<<TT, 128>>>(x, u, gate_w, z_w2, z_b2, Umat);
    k_gateup<<<dim3(FF / 128, EE), 256>>>(x, Wg, Wu);
    k_down<<<dim3(HD / 128, EE), 256>>>(Wd, out);
}

// round 7
// speedup vs baseline: 1.3984x; 1.3984x over previous
#include <cuda_runtime.h>
#include <cstdint>
#include <math.h>

#define TT   512
#define HD   2048
#define EE   32
#define KTOP 4
#define FF   1024
#define NZ   16
#define ZHD  512

__device__ float g_zh[TT * ZHD];
__device__ float g_act[(size_t)EE * TT * FF];
__device__ int   g_cnt[EE];
__device__ int   g_tok[EE * TT];
__device__ float g_wgt[EE * TT];

__device__ __forceinline__ unsigned f2tf(float f) {
    unsigned u;
    asm("cvt.rna.tf32.f32 %0, %1;" : "=r"(u) : "f"(f));
    return u;
}
__device__ __forceinline__ uint32_t smem_u32(const void* p) {
    uint32_t a;
    asm("{ .reg .u64 t; cvta.to.shared.u64 t, %1; cvt.u32.u64 %0, t; }" : "=r"(a) : "l"(p));
    return a;
}
__device__ __forceinline__ void cp16(uint32_t dst, const void* src) {
    asm volatile("cp.async.cg.shared.global [%0], [%1], 16;" :: "r"(dst), "l"(src));
}
#define CP_COMMIT() asm volatile("cp.async.commit_group;" ::: "memory")
#define CP_WAIT2()  asm volatile("cp.async.wait_group 2;" ::: "memory")

__device__ __forceinline__ void mma_tf32(float& d0, float& d1, float& d2, float& d3,
                                         unsigned a0, unsigned a1, unsigned a2, unsigned a3,
                                         unsigned b0, unsigned b1) {
    asm volatile("mma.sync.aligned.m16n8k8.row.col.f32.tf32.tf32.f32 "
                 "{%0,%1,%2,%3}, {%4,%5,%6,%7}, {%8,%9}, {%0,%1,%2,%3};"
                 : "+f"(d0), "+f"(d1), "+f"(d2), "+f"(d3)
                 : "r"(a0), "r"(a1), "r"(a2), "r"(a3), "r"(b0), "r"(b1));
}

// ---------------------------------------------------------------------------
// K0: zero output + expert counters
// ---------------------------------------------------------------------------
__global__ void k_zero(float* __restrict__ out) {
    int i = blockIdx.x * blockDim.x + threadIdx.x;
    if (i < TT * HD) out[i] = 0.0f;
    if (i < EE) g_cnt[i] = 0;
}

// ---------------------------------------------------------------------------
// K1: zh = silu(x @ z_w1^T + b1). M=128, N=64, K=HD (R2 version — small)
// ---------------------------------------------------------------------------
__global__ __launch_bounds__(256, 2) void k_zh(const float* __restrict__ x,
                                               const float* __restrict__ w1,
                                               const float* __restrict__ b1) {
    int m0 = blockIdx.y * 128, n0 = blockIdx.x * 64;
    __shared__ unsigned As[128][20];
    __shared__ unsigned Bs[64][20];
    int tid = threadIdx.x, lane = tid & 31, warp = tid >> 5;
    int wm = warp >> 1, wn = warp & 1;
    int lq = lane >> 2, lr = lane & 3;
    int bn = tid >> 2, bkc = (tid & 3) * 4;

    float acc[2][4][4] = {};
    float4 rA[2], rB;
#pragma unroll
    for (int p = 0; p < 2; p++) {
        int s = tid + p * 256, r = s >> 2, kc = (s & 3) * 4;
        rA[p] = *(const float4*)&x[(size_t)(m0 + r) * HD + kc];
    }
    rB = *(const float4*)&w1[(size_t)(n0 + bn) * HD + bkc];
#pragma unroll
    for (int p = 0; p < 2; p++) {
        int s = tid + p * 256, r = s >> 2, kc = (s & 3) * 4;
        uint4 w = {f2tf(rA[p].x), f2tf(rA[p].y), f2tf(rA[p].z), f2tf(rA[p].w)};
        *(uint4*)&As[r][kc] = w;
    }
    {
        uint4 w = {f2tf(rB.x), f2tf(rB.y), f2tf(rB.z), f2tf(rB.w)};
        *(uint4*)&Bs[bn][bkc] = w;
    }
    __syncthreads();

    for (int k0 = 0; k0 < HD; k0 += 16) {
        bool more = (k0 + 16) < HD;
        if (more) {
            int kn = k0 + 16;
#pragma unroll
            for (int p = 0; p < 2; p++) {
                int s = tid + p * 256, r = s >> 2, kc = (s & 3) * 4;
                rA[p] = *(const float4*)&x[(size_t)(m0 + r) * HD + kn + kc];
            }
            rB = *(const float4*)&w1[(size_t)(n0 + bn) * HD + kn + bkc];
        }
#pragma unroll
        for (int k8 = 0; k8 < 2; k8++) {
            int kb = k8 * 8 + lr;
            unsigned a[2][4];
#pragma unroll
            for (int mi = 0; mi < 2; mi++) {
                int r = wm * 32 + mi * 16 + lq;
                a[mi][0] = As[r][kb];     a[mi][1] = As[r + 8][kb];
                a[mi][2] = As[r][kb + 4]; a[mi][3] = As[r + 8][kb + 4];
            }
#pragma unroll
            for (int ni = 0; ni < 4; ni++) {
                int nn = wn * 32 + ni * 8 + lq;
                unsigned b0 = Bs[nn][kb], b1r = Bs[nn][kb + 4];
#pragma unroll
                for (int mi = 0; mi < 2; mi++)
                    mma_tf32(acc[mi][ni][0], acc[mi][ni][1], acc[mi][ni][2], acc[mi][ni][3],
                             a[mi][0], a[mi][1], a[mi][2], a[mi][3], b0, b1r);
            }
        }
        __syncthreads();
        if (more) {
#pragma unroll
            for (int p = 0; p < 2; p++) {
                int s = tid + p * 256, r = s >> 2, kc = (s & 3) * 4;
                uint4 w = {f2tf(rA[p].x), f2tf(rA[p].y), f2tf(rA[p].z), f2tf(rA[p].w)};
                *(uint4*)&As[r][kc] = w;
            }
            uint4 w = {f2tf(rB.x), f2tf(rB.y), f2tf(rB.z), f2tf(rB.w)};
            *(uint4*)&Bs[bn][bkc] = w;
            __syncthreads();
        }
    }
#pragma unroll
    for (int mi = 0; mi < 2; mi++)
#pragma unroll
        for (int half = 0; half < 2; half++) {
            int r = m0 + wm * 32 + mi * 16 + lq + half * 8;
#pragma unroll
            for (int ni = 0; ni < 4; ni++)
#pragma unroll
                for (int c = 0; c < 2; c++) {
                    int col = n0 + wn * 32 + ni * 8 + lr * 2 + c;
                    float v = acc[mi][ni][half * 2 + c] + b1[col];
                    g_zh[(size_t)r * ZHD + col] = v / (1.0f + expf(-v));
                }
        }
}

// ---------------------------------------------------------------------------
// K2: per-token router (unchanged)
// ---------------------------------------------------------------------------
__global__ __launch_bounds__(128) void k_router(const float* __restrict__ x,
                                                const float* __restrict__ u,
                                                const float* __restrict__ gate_w,
                                                const float* __restrict__ z_w2,
                                                const float* __restrict__ z_b2,
                                                const float* __restrict__ Umat) {
    int t = blockIdx.x;
    __shared__ float xs[HD];
    __shared__ float rl[EE];
    __shared__ float zl[NZ];
    int tid = threadIdx.x, lane = tid & 31, warp = tid >> 5;

    for (int i = tid; i < HD; i += 128) xs[i] = x[t * HD + i];
    __syncthreads();

    for (int e = warp; e < EE; e += 4) {
        float s = 0.0f;
        const float* gw = gate_w + e * HD;
        for (int i = lane; i < HD; i += 32) s += xs[i] * gw[i];
#pragma unroll
        for (int o = 16; o; o >>= 1) s += __shfl_down_sync(0xffffffffu, s, o);
        if (lane == 0) rl[e] = s;
    }
    for (int j = warp; j < NZ; j += 4) {
        float s = 0.0f;
        const float* zw = z_w2 + j * ZHD;
        const float* zh = g_zh + t * ZHD;
        for (int i = lane; i < ZHD; i += 32) s += zh[i] * zw[i];
#pragma unroll
        for (int o = 16; o; o >>= 1) s += __shfl_down_sync(0xffffffffu, s, o);
        if (lane == 0) zl[j] = s + z_b2[j];
    }
    __syncthreads();

    if (tid == 0) {
        int zi = 0;
        float best = -1e30f;
        for (int j = 0; j < NZ; j++) {
            float g = -logf(-logf(u[t * NZ + j]));
            float v = zl[j] + g;
            if (v > best) { best = v; zi = j; }
        }
        float lg[EE];
        float mx = -1e30f;
        for (int e = 0; e < EE; e++) {
            lg[e] = rl[e] + Umat[zi * EE + e];
            mx = fmaxf(mx, lg[e]);
        }
        float sum = 0.0f;
        for (int e = 0; e < EE; e++) { lg[e] = expf(lg[e] - mx); sum += lg[e]; }
        float inv = 1.0f / sum;
        for (int k = 0; k < KTOP; k++) {
            int be = 0;
            float bv = -1.0f;
            for (int e = 0; e < EE; e++)
                if (lg[e] > bv) { bv = lg[e]; be = e; }
            float w = bv * inv;
            lg[be] = -1.0f;
            int pos = atomicAdd(&g_cnt[be], 1);
            g_tok[be * TT + pos] = t;
            g_wgt[be * TT + pos] = w;
        }
    }
}

// ---------------------------------------------------------------------------
// K3: gate/up GEMMs, cp.async 4-stage pipeline, tf32 mma.
// CTA: M=128 gathered tokens x N=64 f-cols of both Wg and Wu. grid (FF/64, EE).
// Dyn smem: toks[128] @0; stage s @1024+s*19456:
//   A raw f32 [128][20] (10240 B) | Bg [16][72] (4608 B) | Bu [16][72]
// A frag: A[r*20+k]  (conflict-free: 20*lq distinct mod 32)
// B frag: B[k*72+n]  (conflict-free: 8*lr+lq covers 32 banks)
// ---------------------------------------------------------------------------
#define GU_ST    19456
#define GU_SMEM  (1024 + 4 * GU_ST)

__global__ __launch_bounds__(256) void k_gateup(const float* __restrict__ x,
                                                const float* __restrict__ Wg,
                                                const float* __restrict__ Wu) {
    extern __shared__ char smem[];
    int e = blockIdx.y;
    int n = g_cnt[e];
    if (n == 0) return;
    int f0 = blockIdx.x * 64;
    uint32_t sb = smem_u32(smem);
    int tid = threadIdx.x, lane = tid & 31, warp = tid >> 5;
    int wm = warp >> 1, wn = warp & 1;
    int lq = lane >> 2, lr = lane & 3;
    int* toks = (int*)smem;
    const float* wg = Wg + (size_t)e * HD * FF + f0;
    const float* wu = Wu + (size_t)e * HD * FF + f0;

    // loader indices
    int ar = tid >> 1, ac0 = tid & 1;          // A: row, first chunk
    int bkk = tid >> 4, bcc = tid & 15;        // B: k-row, 16B chunk

    for (int s0 = 0; s0 < n; s0 += 128) {
        __syncthreads();
        int nt = min(128, n - s0);
        if (tid < 128) toks[tid] = g_tok[e * TT + s0 + ((tid < nt) ? tid : 0)];
        __syncthreads();

        // prologue: tiles 0..2
#pragma unroll
        for (int s = 0; s < 3; s++) {
            uint32_t st = sb + 1024 + s * GU_ST;
            const float* xr = x + (size_t)toks[ar] * HD + s * 16;
            cp16(st + ar * 80 + ac0 * 16, xr + ac0 * 4);
            cp16(st + ar * 80 + (ac0 + 2) * 16, xr + (ac0 + 2) * 4);
            cp16(st + 10240 + bkk * 288 + bcc * 16, wg + (size_t)(s * 16 + bkk) * FF + bcc * 4);
            cp16(st + 14848 + bkk * 288 + bcc * 16, wu + (size_t)(s * 16 + bkk) * FF + bcc * 4);
            CP_COMMIT();
        }

        float accg[2][4][4] = {}, accu[2][4][4] = {};

        for (int i = 0; i < 128; i++) {
            CP_WAIT2();
            __syncthreads();
            int nx = i + 3;
            if (nx < 128) {
                uint32_t st = sb + 1024 + (nx & 3) * GU_ST;
                int kn = nx * 16;
                const float* xr = x + (size_t)toks[ar] * HD + kn;
                cp16(st + ar * 80 + ac0 * 16, xr + ac0 * 4);
                cp16(st + ar * 80 + (ac0 + 2) * 16, xr + (ac0 + 2) * 4);
                cp16(st + 10240 + bkk * 288 + bcc * 16, wg + (size_t)(kn + bkk) * FF + bcc * 4);
                cp16(st + 14848 + bkk * 288 + bcc * 16, wu + (size_t)(kn + bkk) * FF + bcc * 4);
            }
            CP_COMMIT();

            const float* A  = (const float*)(smem + 1024 + (i & 3) * GU_ST);
            const float* Bg = A + 2560;
            const float* Bu = A + 3712;
#pragma unroll
            for (int k8 = 0; k8 < 2; k8++) {
                int kb = k8 * 8 + lr;
                unsigned a[2][4];
#pragma unroll
                for (int mi = 0; mi < 2; mi++) {
                    int r = wm * 32 + mi * 16 + lq;
                    a[mi][0] = f2tf(A[r * 20 + kb]);
                    a[mi][1] = f2tf(A[(r + 8) * 20 + kb]);
                    a[mi][2] = f2tf(A[r * 20 + kb + 4]);
                    a[mi][3] = f2tf(A[(r + 8) * 20 + kb + 4]);
                }
#pragma unroll
                for (int ni = 0; ni < 4; ni++) {
                    int nn = wn * 32 + ni * 8 + lq;
                    unsigned g0 = f2tf(Bg[kb * 72 + nn]), g1 = f2tf(Bg[(kb + 4) * 72 + nn]);
                    unsigned u0 = f2tf(Bu[kb * 72 + nn]), u1 = f2tf(Bu[(kb + 4) * 72 + nn]);
#pragma unroll
                    for (int mi = 0; mi < 2; mi++) {
                        mma_tf32(accg[mi][ni][0], accg[mi][ni][1], accg[mi][ni][2], accg[mi][ni][3],
                                 a[mi][0], a[mi][1], a[mi][2], a[mi][3], g0, g1);
                        mma_tf32(accu[mi][ni][0], accu[mi][ni][1], accu[mi][ni][2], accu[mi][ni][3],
                                 a[mi][0], a[mi][1], a[mi][2], a[mi][3], u0, u1);
                    }
                }
            }
        }

        // epilogue: SwiGLU * comb -> g_act
#pragma unroll
        for (int mi = 0; mi < 2; mi++)
#pragma unroll
            for (int half = 0; half < 2; half++) {
                int r = wm * 32 + mi * 16 + lq + half * 8;
                if (r < nt) {
                    float wc = g_wgt[e * TT + s0 + r];
                    size_t base = ((size_t)e * TT + s0 + r) * FF + f0 + wn * 32;
#pragma unroll
                    for (int ni = 0; ni < 4; ni++)
#pragma unroll
                        for (int c = 0; c < 2; c++) {
                            float gv = accg[mi][ni][half * 2 + c];
                            float uv = accu[mi][ni][half * 2 + c];
                            float act = gv / (1.0f + expf(-gv)) * uv * wc;
                            g_act[base + ni * 8 + lr * 2 + c] = act;
                        }
                }
            }
    }
}

// ---------------------------------------------------------------------------
// K4: down projection, cp.async 4-stage pipeline. M=128 x N=64, K=FF.
// grid (HD/64, EE). Dyn smem: toks @0; stage s @1024+s*14848:
//   A [128][20] (10240 B) | B [16][72] (4608 B)
// ---------------------------------------------------------------------------
#define DN_ST    14848
#define DN_SMEM  (1024 + 4 * DN_ST)

__global__ __launch_bounds__(256) void k_down(const float* __restrict__ Wd,
                                              float* __restrict__ out) {
    extern __shared__ char smem[];
    int e = blockIdx.y;
    int n = g_cnt[e];
    if (n == 0) return;
    int h0 = blockIdx.x * 64;
    uint32_t sb = smem_u32(smem);
    int tid = threadIdx.x, lane = tid & 31, warp = tid >> 5;
    int wm = warp >> 1, wn = warp & 1;
    int lq = lane >> 2, lr = lane & 3;
    int* toks = (int*)smem;
    const float* wd = Wd + (size_t)e * FF * HD + h0;

    int ar = tid >> 1, ac0 = tid & 1;
    int bkk = tid >> 4, bcc = tid & 15;

    for (int s0 = 0; s0 < n; s0 += 128) {
        __syncthreads();
        int nt = min(128, n - s0);
        if (tid < 128) toks[tid] = g_tok[e * TT + s0 + ((tid < nt) ? tid : 0)];
        __syncthreads();

        const float* arow = g_act + ((size_t)e * TT + s0 + ar) * FF;

#pragma unroll
        for (int s = 0; s < 3; s++) {
            uint32_t st = sb + 1024 + s * DN_ST;
            cp16(st + ar * 80 + ac0 * 16, arow + s * 16 + ac0 * 4);
            cp16(st + ar * 80 + (ac0 + 2) * 16, arow + s * 16 + (ac0 + 2) * 4);
            cp16(st + 10240 + bkk * 288 + bcc * 16, wd + (size_t)(s * 16 + bkk) * HD + bcc * 4);
            CP_COMMIT();
        }

        float acc[2][4][4] = {};

        for (int i = 0; i < 64; i++) {
            CP_WAIT2();
            __syncthreads();
            int nx = i + 3;
            if (nx < 64) {
                uint32_t st = sb + 1024 + (nx & 3) * DN_ST;
                int kn = nx * 16;
                cp16(st + ar * 80 + ac0 * 16, arow + kn + ac0 * 4);
                cp16(st + ar * 80 + (ac0 + 2) * 16, arow + kn + (ac0 + 2) * 4);
                cp16(st + 10240 + bkk * 288 + bcc * 16, wd + (size_t)(kn + bkk) * HD + bcc * 4);
            }
            CP_COMMIT();

            const float* A = (const float*)(smem + 1024 + (i & 3) * DN_ST);
            const float* B = A + 2560;
#pragma unroll
            for (int k8 = 0; k8 < 2; k8++) {
                int kb = k8 * 8 + lr;
                unsigned a[2][4];
#pragma unroll
                for (int mi = 0; mi < 2; mi++) {
                    int r = wm * 32 + mi * 16 + lq;
                    a[mi][0] = f2tf(A[r * 20 + kb]);
                    a[mi][1] = f2tf(A[(r + 8) * 20 + kb]);
                    a[mi][2] = f2tf(A[r * 20 + kb + 4]);
                    a[mi][3] = f2tf(A[(r + 8) * 20 + kb + 4]);
                }
#pragma unroll
                for (int ni = 0; ni < 4; ni++) {
                    int nn = wn * 32 + ni * 8 + lq;
                    unsigned b0 = f2tf(B[kb * 72 + nn]), b1r = f2tf(B[(kb + 4) * 72 + nn]);
#pragma unroll
                    for (int mi = 0; mi < 2; mi++)
                        mma_tf32(acc[mi][ni][0], acc[mi][ni][1], acc[mi][ni][2], acc[mi][ni][3],
                                 a[mi][0], a[mi][1], a[mi][2], a[mi][3], b0, b1r);
                }
            }
        }

        // epilogue: atomicAdd into out
#pragma unroll
        for (int mi = 0; mi < 2; mi++)
#pragma unroll
            for (int half = 0; half < 2; half++) {
                int r = wm * 32 + mi * 16 + lq + half * 8;
                if (r < nt) {
                    int t = toks[r];
                    size_t base = (size_t)t * HD + h0 + wn * 32;
#pragma unroll
                    for (int ni = 0; ni < 4; ni++)
#pragma unroll
                        for (int c = 0; c < 2; c++)
                            atomicAdd(&out[base + ni * 8 + lr * 2 + c],
                                      acc[mi][ni][half * 2 + c]);
                }
            }
    }
}

// ---------------------------------------------------------------------------
// launch
// ---------------------------------------------------------------------------
extern "C" void kernel_launch(void* const* d_in, const int* in_sizes, int n_in,
                              void* d_out, int out_size) {
    const float* x      = (const float*)d_in[0];
    const float* u      = (const float*)d_in[1];
    const float* gate_w = (const float*)d_in[2];
    const float* z_w1   = (const float*)d_in[3];
    const float* z_b1   = (const float*)d_in[4];
    const float* z_w2   = (const float*)d_in[5];
    const float* z_b2   = (const float*)d_in[6];
    const float* Umat   = (const float*)d_in[7];
    const float* Wg     = (const float*)d_in[8];
    const float* Wu     = (const float*)d_in[9];
    const float* Wd     = (const float*)d_in[10];
    float* out = (float*)d_out;

    cudaFuncSetAttribute(k_gateup, cudaFuncAttributeMaxDynamicSharedMemorySize, GU_SMEM);
    cudaFuncSetAttribute(k_down,   cudaFuncAttributeMaxDynamicSharedMemorySize, DN_SMEM);

    k_zero<<<(TT * HD + 255) / 256, 256>>>(out);
    k_zh<<<dim3(ZHD / 64, TT / 128), 256>>>(x, z_w1, z_b1);
    k_router<<<TT, 128>>>(x, u, gate_w, z_w2, z_b2, Umat);
    k_gateup<<<dim3(FF / 64, EE), 256, GU_SMEM>>>(x, Wg, Wu);
    k_down<<<dim3(HD / 64, EE), 256, DN_SMEM>>>(Wd, out);
}

// round 9
// speedup vs baseline: 1.7777x; 1.2713x over previous
#include <cuda_runtime.h>
#include <cstdint>
#include <math.h>

#define TT   512
#define HD   2048
#define EE   32
#define KTOP 4
#define FF   1024
#define NZ   16
#define ZHD  512

__device__ float g_zh[TT * ZHD];
__device__ float g_act[(size_t)EE * TT * FF];
__device__ int   g_cnt[EE];
__device__ int   g_tok[EE * TT];
__device__ float g_wgt[EE * TT];

__device__ __forceinline__ unsigned f2tf(float f) {
    unsigned u;
    asm("cvt.rna.tf32.f32 %0, %1;" : "=r"(u) : "f"(f));
    return u;
}
// pack two f32 into f16x2: lo = first arg, hi = second arg
__device__ __forceinline__ unsigned pack_h2(float lo, float hi) {
    unsigned d;
    asm("cvt.rn.f16x2.f32 %0, %1, %2;" : "=r"(d) : "f"(hi), "f"(lo));
    return d;
}
__device__ __forceinline__ uint32_t smem_u32(const void* p) {
    uint32_t a;
    asm("{ .reg .u64 t; cvta.to.shared.u64 t, %1; cvt.u32.u64 %0, t; }" : "=r"(a) : "l"(p));
    return a;
}
__device__ __forceinline__ void cp16(uint32_t dst, const void* src) {
    asm volatile("cp.async.cg.shared.global [%0], [%1], 16;" :: "r"(dst), "l"(src));
}
#define CP_COMMIT() asm volatile("cp.async.commit_group;" ::: "memory")
#define CP_WAIT2()  asm volatile("cp.async.wait_group 2;" ::: "memory")

__device__ __forceinline__ void mma_tf32(float& d0, float& d1, float& d2, float& d3,
                                         unsigned a0, unsigned a1, unsigned a2, unsigned a3,
                                         unsigned b0, unsigned b1) {
    asm volatile("mma.sync.aligned.m16n8k8.row.col.f32.tf32.tf32.f32 "
                 "{%0,%1,%2,%3}, {%4,%5,%6,%7}, {%8,%9}, {%0,%1,%2,%3};"
                 : "+f"(d0), "+f"(d1), "+f"(d2), "+f"(d3)
                 : "r"(a0), "r"(a1), "r"(a2), "r"(a3), "r"(b0), "r"(b1));
}
__device__ __forceinline__ void mma_f16(float& d0, float& d1, float& d2, float& d3,
                                        unsigned a0, unsigned a1, unsigned a2, unsigned a3,
                                        unsigned b0, unsigned b1) {
    asm volatile("mma.sync.aligned.m16n8k16.row.col.f32.f16.f16.f32 "
                 "{%0,%1,%2,%3}, {%4,%5,%6,%7}, {%8,%9}, {%0,%1,%2,%3};"
                 : "+f"(d0), "+f"(d1), "+f"(d2), "+f"(d3)
                 : "r"(a0), "r"(a1), "r"(a2), "r"(a3), "r"(b0), "r"(b1));
}

// ---------------------------------------------------------------------------
// K0: zero output + expert counters
// ---------------------------------------------------------------------------
__global__ void k_zero(float* __restrict__ out) {
    int i = blockIdx.x * blockDim.x + threadIdx.x;
    if (i < TT * HD) out[i] = 0.0f;
    if (i < EE) g_cnt[i] = 0;
}

// ---------------------------------------------------------------------------
// K1: zh = silu(x @ z_w1^T + b1). tf32 (small; unchanged)
// ---------------------------------------------------------------------------
__global__ __launch_bounds__(256, 2) void k_zh(const float* __restrict__ x,
                                               const float* __restrict__ w1,
                                               const float* __restrict__ b1) {
    int m0 = blockIdx.y * 128, n0 = blockIdx.x * 64;
    __shared__ unsigned As[128][20];
    __shared__ unsigned Bs[64][20];
    int tid = threadIdx.x, lane = tid & 31, warp = tid >> 5;
    int wm = warp >> 1, wn = warp & 1;
    int lq = lane >> 2, lr = lane & 3;
    int bn = tid >> 2, bkc = (tid & 3) * 4;

    float acc[2][4][4] = {};
    float4 rA[2], rB;
#pragma unroll
    for (int p = 0; p < 2; p++) {
        int s = tid + p * 256, r = s >> 2, kc = (s & 3) * 4;
        rA[p] = *(const float4*)&x[(size_t)(m0 + r) * HD + kc];
    }
    rB = *(const float4*)&w1[(size_t)(n0 + bn) * HD + bkc];
#pragma unroll
    for (int p = 0; p < 2; p++) {
        int s = tid + p * 256, r = s >> 2, kc = (s & 3) * 4;
        uint4 w = {f2tf(rA[p].x), f2tf(rA[p].y), f2tf(rA[p].z), f2tf(rA[p].w)};
        *(uint4*)&As[r][kc] = w;
    }
    {
        uint4 w = {f2tf(rB.x), f2tf(rB.y), f2tf(rB.z), f2tf(rB.w)};
        *(uint4*)&Bs[bn][bkc] = w;
    }
    __syncthreads();

    for (int k0 = 0; k0 < HD; k0 += 16) {
        bool more = (k0 + 16) < HD;
        if (more) {
            int kn = k0 + 16;
#pragma unroll
            for (int p = 0; p < 2; p++) {
                int s = tid + p * 256, r = s >> 2, kc = (s & 3) * 4;
                rA[p] = *(const float4*)&x[(size_t)(m0 + r) * HD + kn + kc];
            }
            rB = *(const float4*)&w1[(size_t)(n0 + bn) * HD + kn + bkc];
        }
#pragma unroll
        for (int k8 = 0; k8 < 2; k8++) {
            int kb = k8 * 8 + lr;
            unsigned a[2][4];
#pragma unroll
            for (int mi = 0; mi < 2; mi++) {
                int r = wm * 32 + mi * 16 + lq;
                a[mi][0] = As[r][kb];     a[mi][1] = As[r + 8][kb];
                a[mi][2] = As[r][kb + 4]; a[mi][3] = As[r + 8][kb + 4];
            }
#pragma unroll
            for (int ni = 0; ni < 4; ni++) {
                int nn = wn * 32 + ni * 8 + lq;
                unsigned b0 = Bs[nn][kb], b1r = Bs[nn][kb + 4];
#pragma unroll
                for (int mi = 0; mi < 2; mi++)
                    mma_tf32(acc[mi][ni][0], acc[mi][ni][1], acc[mi][ni][2], acc[mi][ni][3],
                             a[mi][0], a[mi][1], a[mi][2], a[mi][3], b0, b1r);
            }
        }
        __syncthreads();
        if (more) {
#pragma unroll
            for (int p = 0; p < 2; p++) {
                int s = tid + p * 256, r = s >> 2, kc = (s & 3) * 4;
                uint4 w = {f2tf(rA[p].x), f2tf(rA[p].y), f2tf(rA[p].z), f2tf(rA[p].w)};
                *(uint4*)&As[r][kc] = w;
            }
            uint4 w = {f2tf(rB.x), f2tf(rB.y), f2tf(rB.z), f2tf(rB.w)};
            *(uint4*)&Bs[bn][bkc] = w;
            __syncthreads();
        }
    }
#pragma unroll
    for (int mi = 0; mi < 2; mi++)
#pragma unroll
        for (int half = 0; half < 2; half++) {
            int r = m0 + wm * 32 + mi * 16 + lq + half * 8;
#pragma unroll
            for (int ni = 0; ni < 4; ni++)
#pragma unroll
                for (int c = 0; c < 2; c++) {
                    int col = n0 + wn * 32 + ni * 8 + lr * 2 + c;
                    float v = acc[mi][ni][half * 2 + c] + b1[col];
                    g_zh[(size_t)r * ZHD + col] = v / (1.0f + expf(-v));
                }
        }
}

// ---------------------------------------------------------------------------
// K2: per-token router (unchanged)
// ---------------------------------------------------------------------------
__global__ __launch_bounds__(128) void k_router(const float* __restrict__ x,
                                                const float* __restrict__ u,
                                                const float* __restrict__ gate_w,
                                                const float* __restrict__ z_w2,
                                                const float* __restrict__ z_b2,
                                                const float* __restrict__ Umat) {
    int t = blockIdx.x;
    __shared__ float xs[HD];
    __shared__ float rl[EE];
    __shared__ float zl[NZ];
    int tid = threadIdx.x, lane = tid & 31, warp = tid >> 5;

    for (int i = tid; i < HD; i += 128) xs[i] = x[t * HD + i];
    __syncthreads();

    for (int e = warp; e < EE; e += 4) {
        float s = 0.0f;
        const float* gw = gate_w + e * HD;
        for (int i = lane; i < HD; i += 32) s += xs[i] * gw[i];
#pragma unroll
        for (int o = 16; o; o >>= 1) s += __shfl_down_sync(0xffffffffu, s, o);
        if (lane == 0) rl[e] = s;
    }
    for (int j = warp; j < NZ; j += 4) {
        float s = 0.0f;
        const float* zw = z_w2 + j * ZHD;
        const float* zh = g_zh + t * ZHD;
        for (int i = lane; i < ZHD; i += 32) s += zh[i] * zw[i];
#pragma unroll
        for (int o = 16; o; o >>= 1) s += __shfl_down_sync(0xffffffffu, s, o);
        if (lane == 0) zl[j] = s + z_b2[j];
    }
    __syncthreads();

    if (tid == 0) {
        int zi = 0;
        float best = -1e30f;
        for (int j = 0; j < NZ; j++) {
            float g = -logf(-logf(u[t * NZ + j]));
            float v = zl[j] + g;
            if (v > best) { best = v; zi = j; }
        }
        float lg[EE];
        float mx = -1e30f;
        for (int e = 0; e < EE; e++) {
            lg[e] = rl[e] + Umat[zi * EE + e];
            mx = fmaxf(mx, lg[e]);
        }
        float sum = 0.0f;
        for (int e = 0; e < EE; e++) { lg[e] = expf(lg[e] - mx); sum += lg[e]; }
        float inv = 1.0f / sum;
        for (int k = 0; k < KTOP; k++) {
            int be = 0;
            float bv = -1.0f;
            for (int e = 0; e < EE; e++)
                if (lg[e] > bv) { bv = lg[e]; be = e; }
            float w = bv * inv;
            lg[be] = -1.0f;
            int pos = atomicAdd(&g_cnt[be], 1);
            g_tok[be * TT + pos] = t;
            g_wgt[be * TT + pos] = w;
        }
    }
}

// ---------------------------------------------------------------------------
// K3: gate/up, cp.async 4-stage pipeline, fp16 m16n8k16 mma.
// CTA: M=128 tokens x N=64 f-cols of both Wg and Wu. grid (FF/64, EE).
// Dyn smem: toks[128] @0; stage s @1024 + s*20992:
//   A f32 [128][24w] (12288 B) | Bg [16][68w] (4352 B) | Bu [16][68w]
// A frag LDS.64 stride-24 conflict-free; B LDS.32 stride-68 conflict-free.
// ---------------------------------------------------------------------------
#define GU_ST    20992
#define GU_SMEM  (1024 + 4 * GU_ST)

__global__ __launch_bounds__(256) void k_gateup(const float* __restrict__ x,
                                                const float* __restrict__ Wg,
                                                const float* __restrict__ Wu) {
    extern __shared__ char smem[];
    int e = blockIdx.y;
    int n = g_cnt[e];
    if (n == 0) return;
    int f0 = blockIdx.x * 64;
    uint32_t sb = smem_u32(smem);
    int tid = threadIdx.x, lane = tid & 31, warp = tid >> 5;
    int wm = warp >> 1, wn = warp & 1;
    int lq = lane >> 2, lr = lane & 3;
    int* toks = (int*)smem;
    const float* wg = Wg + (size_t)e * HD * FF + f0;
    const float* wu = Wu + (size_t)e * HD * FF + f0;

    int ar = tid >> 1, ac0 = tid & 1;
    int bkk = tid >> 4, bcc = tid & 15;

    for (int s0 = 0; s0 < n; s0 += 128) {
        __syncthreads();
        int nt = min(128, n - s0);
        if (tid < 128) toks[tid] = g_tok[e * TT + s0 + ((tid < nt) ? tid : 0)];
        __syncthreads();

#pragma unroll
        for (int s = 0; s < 3; s++) {
            uint32_t st = sb + 1024 + s * GU_ST;
            const float* xr = x + (size_t)toks[ar] * HD + s * 16;
            cp16(st + ar * 96 + ac0 * 16, xr + ac0 * 4);
            cp16(st + ar * 96 + (ac0 + 2) * 16, xr + (ac0 + 2) * 4);
            cp16(st + 12288 + bkk * 272 + bcc * 16, wg + (size_t)(s * 16 + bkk) * FF + bcc * 4);
            cp16(st + 16640 + bkk * 272 + bcc * 16, wu + (size_t)(s * 16 + bkk) * FF + bcc * 4);
            CP_COMMIT();
        }

        float accg[2][4][4] = {}, accu[2][4][4] = {};

        for (int i = 0; i < 128; i++) {
            CP_WAIT2();
            __syncthreads();
            int nx = i + 3;
            if (nx < 128) {
                uint32_t st = sb + 1024 + (nx & 3) * GU_ST;
                int kn = nx * 16;
                const float* xr = x + (size_t)toks[ar] * HD + kn;
                cp16(st + ar * 96 + ac0 * 16, xr + ac0 * 4);
                cp16(st + ar * 96 + (ac0 + 2) * 16, xr + (ac0 + 2) * 4);
                cp16(st + 12288 + bkk * 272 + bcc * 16, wg + (size_t)(kn + bkk) * FF + bcc * 4);
                cp16(st + 16640 + bkk * 272 + bcc * 16, wu + (size_t)(kn + bkk) * FF + bcc * 4);
            }
            CP_COMMIT();

            const float* A  = (const float*)(smem + 1024 + (i & 3) * GU_ST);
            const float* Bg = A + 3072;
            const float* Bu = A + 4160;

            unsigned a[2][4];
#pragma unroll
            for (int mi = 0; mi < 2; mi++) {
                int r = wm * 32 + mi * 16 + lq;
                float2 v0 = *(const float2*)(A + r * 24 + 2 * lr);
                float2 v1 = *(const float2*)(A + (r + 8) * 24 + 2 * lr);
                float2 v2 = *(const float2*)(A + r * 24 + 2 * lr + 8);
                float2 v3 = *(const float2*)(A + (r + 8) * 24 + 2 * lr + 8);
                a[mi][0] = pack_h2(v0.x, v0.y);
                a[mi][1] = pack_h2(v1.x, v1.y);
                a[mi][2] = pack_h2(v2.x, v2.y);
                a[mi][3] = pack_h2(v3.x, v3.y);
            }
#pragma unroll
            for (int ni = 0; ni < 4; ni++) {
                int nn = wn * 32 + ni * 8 + lq;
                unsigned g0 = pack_h2(Bg[(2 * lr) * 68 + nn],     Bg[(2 * lr + 1) * 68 + nn]);
                unsigned g1 = pack_h2(Bg[(2 * lr + 8) * 68 + nn], Bg[(2 * lr + 9) * 68 + nn]);
                unsigned u0 = pack_h2(Bu[(2 * lr) * 68 + nn],     Bu[(2 * lr + 1) * 68 + nn]);
                unsigned u1 = pack_h2(Bu[(2 * lr + 8) * 68 + nn], Bu[(2 * lr + 9) * 68 + nn]);
#pragma unroll
                for (int mi = 0; mi < 2; mi++) {
                    mma_f16(accg[mi][ni][0], accg[mi][ni][1], accg[mi][ni][2], accg[mi][ni][3],
                            a[mi][0], a[mi][1], a[mi][2], a[mi][3], g0, g1);
                    mma_f16(accu[mi][ni][0], accu[mi][ni][1], accu[mi][ni][2], accu[mi][ni][3],
                            a[mi][0], a[mi][1], a[mi][2], a[mi][3], u0, u1);
                }
            }
        }

        // epilogue: SwiGLU * comb -> g_act
#pragma unroll
        for (int mi = 0; mi < 2; mi++)
#pragma unroll
            for (int half = 0; half < 2; half++) {
                int r = wm * 32 + mi * 16 + lq + half * 8;
                if (r < nt) {
                    float wc = g_wgt[e * TT + s0 + r];
                    size_t base = ((size_t)e * TT + s0 + r) * FF + f0 + wn * 32;
#pragma unroll
                    for (int ni = 0; ni < 4; ni++)
#pragma unroll
                        for (int c = 0; c < 2; c++) {
                            float gv = accg[mi][ni][half * 2 + c];
                            float uv = accu[mi][ni][half * 2 + c];
                            float act = gv / (1.0f + expf(-gv)) * uv * wc;
                            g_act[base + ni * 8 + lr * 2 + c] = act;
                        }
                }
            }
    }
}

// ---------------------------------------------------------------------------
// K4: down projection, cp.async 4-stage pipeline, fp16 mma. M=128 x N=64, K=FF.
// grid (HD/64, EE). Dyn smem: toks @0; stage s @1024 + s*16640:
//   A [128][24w] (12288 B) | B [16][68w] (4352 B)
// ---------------------------------------------------------------------------
#define DN_ST    16640
#define DN_SMEM  (1024 + 4 * DN_ST)

__global__ __launch_bounds__(256) void k_down(const float* __restrict__ Wd,
                                              float* __restrict__ out) {
    extern __shared__ char smem[];
    int e = blockIdx.y;
    int n = g_cnt[e];
    if (n == 0) return;
    int h0 = blockIdx.x * 64;
    uint32_t sb = smem_u32(smem);
    int tid = threadIdx.x, lane = tid & 31, warp = tid >> 5;
    int wm = warp >> 1, wn = warp & 1;
    int lq = lane >> 2, lr = lane & 3;
    int* toks = (int*)smem;
    const float* wd = Wd + (size_t)e * FF * HD + h0;

    int ar = tid >> 1, ac0 = tid & 1;
    int bkk = tid >> 4, bcc = tid & 15;

    for (int s0 = 0; s0 < n; s0 += 128) {
        __syncthreads();
        int nt = min(128, n - s0);
        if (tid < 128) toks[tid] = g_tok[e * TT + s0 + ((tid < nt) ? tid : 0)];
        __syncthreads();

        const float* arow = g_act + ((size_t)e * TT + s0 + ar) * FF;

#pragma unroll
        for (int s = 0; s < 3; s++) {
            uint32_t st = sb + 1024 + s * DN_ST;
            cp16(st + ar * 96 + ac0 * 16, arow + s * 16 + ac0 * 4);
            cp16(st + ar * 96 + (ac0 + 2) * 16, arow + s * 16 + (ac0 + 2) * 4);
            cp16(st + 12288 + bkk * 272 + bcc * 16, wd + (size_t)(s * 16 + bkk) * HD + bcc * 4);
            CP_COMMIT();
        }

        float acc[2][4][4] = {};

        for (int i = 0; i < 64; i++) {
            CP_WAIT2();
            __syncthreads();
            int nx = i + 3;
            if (nx < 64) {
                uint32_t st = sb + 1024 + (nx & 3) * DN_ST;
                int kn = nx * 16;
                cp16(st + ar * 96 + ac0 * 16, arow + kn + ac0 * 4);
                cp16(st + ar * 96 + (ac0 + 2) * 16, arow + kn + (ac0 + 2) * 4);
                cp16(st + 12288 + bkk * 272 + bcc * 16, wd + (size_t)(kn + bkk) * HD + bcc * 4);
            }
            CP_COMMIT();

            const float* A = (const float*)(smem + 1024 + (i & 3) * DN_ST);
            const float* B = A + 3072;

            unsigned a[2][4];
#pragma unroll
            for (int mi = 0; mi < 2; mi++) {
                int r = wm * 32 + mi * 16 + lq;
                float2 v0 = *(const float2*)(A + r * 24 + 2 * lr);
                float2 v1 = *(const float2*)(A + (r + 8) * 24 + 2 * lr);
                float2 v2 = *(const float2*)(A + r * 24 + 2 * lr + 8);
                float2 v3 = *(const float2*)(A + (r + 8) * 24 + 2 * lr + 8);
                a[mi][0] = pack_h2(v0.x, v0.y);
                a[mi][1] = pack_h2(v1.x, v1.y);
                a[mi][2] = pack_h2(v2.x, v2.y);
                a[mi][3] = pack_h2(v3.x, v3.y);
            }
#pragma unroll
            for (int ni = 0; ni < 4; ni++) {
                int nn = wn * 32 + ni * 8 + lq;
                unsigned b0 = pack_h2(B[(2 * lr) * 68 + nn],     B[(2 * lr + 1) * 68 + nn]);
                unsigned b1 = pack_h2(B[(2 * lr + 8) * 68 + nn], B[(2 * lr + 9) * 68 + nn]);
#pragma unroll
                for (int mi = 0; mi < 2; mi++)
                    mma_f16(acc[mi][ni][0], acc[mi][ni][1], acc[mi][ni][2], acc[mi][ni][3],
                            a[mi][0], a[mi][1], a[mi][2], a[mi][3], b0, b1);
            }
        }

        // epilogue: atomicAdd into out
#pragma unroll
        for (int mi = 0; mi < 2; mi++)
#pragma unroll
            for (int half = 0; half < 2; half++) {
                int r = wm * 32 + mi * 16 + lq + half * 8;
                if (r < nt) {
                    int t = toks[r];
                    size_t base = (size_t)t * HD + h0 + wn * 32;
#pragma unroll
                    for (int ni = 0; ni < 4; ni++)
#pragma unroll
                        for (int c = 0; c < 2; c++)
                            atomicAdd(&out[base + ni * 8 + lr * 2 + c],
                                      acc[mi][ni][half * 2 + c]);
                }
            }
    }
}

// ---------------------------------------------------------------------------
// launch
// ---------------------------------------------------------------------------
extern "C" void kernel_launch(void* const* d_in, const int* in_sizes, int n_in,
                              void* d_out, int out_size) {
    const float* x      = (const float*)d_in[0];
    const float* u      = (const float*)d_in[1];
    const float* gate_w = (const float*)d_in[2];
    const float* z_w1   = (const float*)d_in[3];
    const float* z_b1   = (const float*)d_in[4];
    const float* z_w2   = (const float*)d_in[5];
    const float* z_b2   = (const float*)d_in[6];
    const float* Umat   = (const float*)d_in[7];
    const float* Wg     = (const float*)d_in[8];
    const float* Wu     = (const float*)d_in[9];
    const float* Wd     = (const float*)d_in[10];
    float* out = (float*)d_out;

    cudaFuncSetAttribute(k_gateup, cudaFuncAttributeMaxDynamicSharedMemorySize, GU_SMEM);
    cudaFuncSetAttribute(k_down,   cudaFuncAttributeMaxDynamicSharedMemorySize, DN_SMEM);

    k_zero<<<(TT * HD + 255) / 256, 256>>>(out);
    k_zh<<<dim3(ZHD / 64, TT / 128), 256>>>(x, z_w1, z_b1);
    k_router<<<TT, 128>>>(x, u, gate_w, z_w2, z_b2, Umat);
    k_gateup<<<dim3(FF / 64, EE), 256, GU_SMEM>>>(x, Wg, Wu);
    k_down<<<dim3(HD / 64, EE), 256, DN_SMEM>>>(Wd, out);
}

// round 11
// speedup vs baseline: 1.8218x; 1.0248x over previous
#include <cuda_runtime.h>
#include <cuda_fp16.h>
#include <cstdint>
#include <math.h>

#define TT   512
#define HD   2048
#define EE   32
#define KTOP 4
#define FF   1024
#define NZ   16
#define ZHD  512

__device__ float  g_zh[TT * ZHD];
__device__ __half g_xh[TT * HD];                      // fp16 copy of x (2 MB)
__device__ __half g_acth[(size_t)EE * TT * FF];       // fp16 activations (33 MB)
__device__ int    g_cnt[EE];
__device__ int    g_tok[EE * TT];
__device__ float  g_wgt[EE * TT];

__device__ __forceinline__ unsigned f2tf(float f) {
    unsigned u;
    asm("cvt.rna.tf32.f32 %0, %1;" : "=r"(u) : "f"(f));
    return u;
}
// pack two f32 into f16x2: first arg -> low half
__device__ __forceinline__ unsigned pack_h2(float lo, float hi) {
    unsigned d;
    asm("cvt.rn.f16x2.f32 %0, %1, %2;" : "=r"(d) : "f"(hi), "f"(lo));
    return d;
}
__device__ __forceinline__ uint32_t smem_u32(const void* p) {
    uint32_t a;
    asm("{ .reg .u64 t; cvta.to.shared.u64 t, %1; cvt.u32.u64 %0, t; }" : "=r"(a) : "l"(p));
    return a;
}
__device__ __forceinline__ void cp16(uint32_t dst, const void* src) {
    asm volatile("cp.async.cg.shared.global [%0], [%1], 16;" :: "r"(dst), "l"(src));
}
#define CP_COMMIT() asm volatile("cp.async.commit_group;" ::: "memory")
#define CP_WAIT4()  asm volatile("cp.async.wait_group 4;" ::: "memory")

__device__ __forceinline__ void mma_tf32(float& d0, float& d1, float& d2, float& d3,
                                         unsigned a0, unsigned a1, unsigned a2, unsigned a3,
                                         unsigned b0, unsigned b1) {
    asm volatile("mma.sync.aligned.m16n8k8.row.col.f32.tf32.tf32.f32 "
                 "{%0,%1,%2,%3}, {%4,%5,%6,%7}, {%8,%9}, {%0,%1,%2,%3};"
                 : "+f"(d0), "+f"(d1), "+f"(d2), "+f"(d3)
                 : "r"(a0), "r"(a1), "r"(a2), "r"(a3), "r"(b0), "r"(b1));
}
__device__ __forceinline__ void mma_f16(float& d0, float& d1, float& d2, float& d3,
                                        unsigned a0, unsigned a1, unsigned a2, unsigned a3,
                                        unsigned b0, unsigned b1) {
    asm volatile("mma.sync.aligned.m16n8k16.row.col.f32.f16.f16.f32 "
                 "{%0,%1,%2,%3}, {%4,%5,%6,%7}, {%8,%9}, {%0,%1,%2,%3};"
                 : "+f"(d0), "+f"(d1), "+f"(d2), "+f"(d3)
                 : "r"(a0), "r"(a1), "r"(a2), "r"(a3), "r"(b0), "r"(b1));
}

// ---------------------------------------------------------------------------
// K0: zero output + counters + fp16 copy of x
// ---------------------------------------------------------------------------
__global__ void k_zero(float* __restrict__ out, const float* __restrict__ x) {
    int i = blockIdx.x * blockDim.x + threadIdx.x;
    if (i < TT * HD) {
        out[i] = 0.0f;
        g_xh[i] = __float2half_rn(x[i]);
    }
    if (i < EE) g_cnt[i] = 0;
}

// ---------------------------------------------------------------------------
// K1: zh = silu(x @ z_w1^T + b1). tf32 (small; unchanged)
// ---------------------------------------------------------------------------
__global__ __launch_bounds__(256, 2) void k_zh(const float* __restrict__ x,
                                               const float* __restrict__ w1,
                                               const float* __restrict__ b1) {
    int m0 = blockIdx.y * 128, n0 = blockIdx.x * 64;
    __shared__ unsigned As[128][20];
    __shared__ unsigned Bs[64][20];
    int tid = threadIdx.x, lane = tid & 31, warp = tid >> 5;
    int wm = warp >> 1, wn = warp & 1;
    int lq = lane >> 2, lr = lane & 3;
    int bn = tid >> 2, bkc = (tid & 3) * 4;

    float acc[2][4][4] = {};
    float4 rA[2], rB;
#pragma unroll
    for (int p = 0; p < 2; p++) {
        int s = tid + p * 256, r = s >> 2, kc = (s & 3) * 4;
        rA[p] = *(const float4*)&x[(size_t)(m0 + r) * HD + kc];
    }
    rB = *(const float4*)&w1[(size_t)(n0 + bn) * HD + bkc];
#pragma unroll
    for (int p = 0; p < 2; p++) {
        int s = tid + p * 256, r = s >> 2, kc = (s & 3) * 4;
        uint4 w = {f2tf(rA[p].x), f2tf(rA[p].y), f2tf(rA[p].z), f2tf(rA[p].w)};
        *(uint4*)&As[r][kc] = w;
    }
    {
        uint4 w = {f2tf(rB.x), f2tf(rB.y), f2tf(rB.z), f2tf(rB.w)};
        *(uint4*)&Bs[bn][bkc] = w;
    }
    __syncthreads();

    for (int k0 = 0; k0 < HD; k0 += 16) {
        bool more = (k0 + 16) < HD;
        if (more) {
            int kn = k0 + 16;
#pragma unroll
            for (int p = 0; p < 2; p++) {
                int s = tid + p * 256, r = s >> 2, kc = (s & 3) * 4;
                rA[p] = *(const float4*)&x[(size_t)(m0 + r) * HD + kn + kc];
            }
            rB = *(const float4*)&w1[(size_t)(n0 + bn) * HD + kn + bkc];
        }
#pragma unroll
        for (int k8 = 0; k8 < 2; k8++) {
            int kb = k8 * 8 + lr;
            unsigned a[2][4];
#pragma unroll
            for (int mi = 0; mi < 2; mi++) {
                int r = wm * 32 + mi * 16 + lq;
                a[mi][0] = As[r][kb];     a[mi][1] = As[r + 8][kb];
                a[mi][2] = As[r][kb + 4]; a[mi][3] = As[r + 8][kb + 4];
            }
#pragma unroll
            for (int ni = 0; ni < 4; ni++) {
                int nn = wn * 32 + ni * 8 + lq;
                unsigned b0 = Bs[nn][kb], b1r = Bs[nn][kb + 4];
#pragma unroll
                for (int mi = 0; mi < 2; mi++)
                    mma_tf32(acc[mi][ni][0], acc[mi][ni][1], acc[mi][ni][2], acc[mi][ni][3],
                             a[mi][0], a[mi][1], a[mi][2], a[mi][3], b0, b1r);
            }
        }
        __syncthreads();
        if (more) {
#pragma unroll
            for (int p = 0; p < 2; p++) {
                int s = tid + p * 256, r = s >> 2, kc = (s & 3) * 4;
                uint4 w = {f2tf(rA[p].x), f2tf(rA[p].y), f2tf(rA[p].z), f2tf(rA[p].w)};
                *(uint4*)&As[r][kc] = w;
            }
            uint4 w = {f2tf(rB.x), f2tf(rB.y), f2tf(rB.z), f2tf(rB.w)};
            *(uint4*)&Bs[bn][bkc] = w;
            __syncthreads();
        }
    }
#pragma unroll
    for (int mi = 0; mi < 2; mi++)
#pragma unroll
        for (int half = 0; half < 2; half++) {
            int r = m0 + wm * 32 + mi * 16 + lq + half * 8;
#pragma unroll
            for (int ni = 0; ni < 4; ni++)
#pragma unroll
                for (int c = 0; c < 2; c++) {
                    int col = n0 + wn * 32 + ni * 8 + lr * 2 + c;
                    float v = acc[mi][ni][half * 2 + c] + b1[col];
                    g_zh[(size_t)r * ZHD + col] = v / (1.0f + expf(-v));
                }
        }
}

// ---------------------------------------------------------------------------
// K2: per-token router (unchanged)
// ---------------------------------------------------------------------------
__global__ __launch_bounds__(128) void k_router(const float* __restrict__ x,
                                                const float* __restrict__ u,
                                                const float* __restrict__ gate_w,
                                                const float* __restrict__ z_w2,
                                                const float* __restrict__ z_b2,
                                                const float* __restrict__ Umat) {
    int t = blockIdx.x;
    __shared__ float xs[HD];
    __shared__ float rl[EE];
    __shared__ float zl[NZ];
    int tid = threadIdx.x, lane = tid & 31, warp = tid >> 5;

    for (int i = tid; i < HD; i += 128) xs[i] = x[t * HD + i];
    __syncthreads();

    for (int e = warp; e < EE; e += 4) {
        float s = 0.0f;
        const float* gw = gate_w + e * HD;
        for (int i = lane; i < HD; i += 32) s += xs[i] * gw[i];
#pragma unroll
        for (int o = 16; o; o >>= 1) s += __shfl_down_sync(0xffffffffu, s, o);
        if (lane == 0) rl[e] = s;
    }
    for (int j = warp; j < NZ; j += 4) {
        float s = 0.0f;
        const float* zw = z_w2 + j * ZHD;
        const float* zh = g_zh + t * ZHD;
        for (int i = lane; i < ZHD; i += 32) s += zh[i] * zw[i];
#pragma unroll
        for (int o = 16; o; o >>= 1) s += __shfl_down_sync(0xffffffffu, s, o);
        if (lane == 0) zl[j] = s + z_b2[j];
    }
    __syncthreads();

    if (tid == 0) {
        int zi = 0;
        float best = -1e30f;
        for (int j = 0; j < NZ; j++) {
            float g = -logf(-logf(u[t * NZ + j]));
            float v = zl[j] + g;
            if (v > best) { best = v; zi = j; }
        }
        float lg[EE];
        float mx = -1e30f;
        for (int e = 0; e < EE; e++) {
            lg[e] = rl[e] + Umat[zi * EE + e];
            mx = fmaxf(mx, lg[e]);
        }
        float sum = 0.0f;
        for (int e = 0; e < EE; e++) { lg[e] = expf(lg[e] - mx); sum += lg[e]; }
        float inv = 1.0f / sum;
        for (int k = 0; k < KTOP; k++) {
            int be = 0;
            float bv = -1.0f;
            for (int e = 0; e < EE; e++)
                if (lg[e] > bv) { bv = lg[e]; be = e; }
            float w = bv * inv;
            lg[be] = -1.0f;
            int pos = atomicAdd(&g_cnt[be], 1);
            g_tok[be * TT + pos] = t;
            g_wgt[be * TT + pos] = w;
        }
    }
}

// ---------------------------------------------------------------------------
// K3: gate/up, 6-stage cp.async pipeline, fp16 mma. A staged fp16 from g_xh.
// CTA: M=128 tokens x N=64 f-cols of both Wg and Wu. grid (FF/64, EE).
// Stage (14848 B): A fp16 [128 rows][12w stride, 8w data] (6144 B)
//                | Bg f32 [16][68w] (4352 B) | Bu f32 [16][68w] (4352 B)
// A frag LDS.32 @ word r*12+lr (+4): conflict-free. B stride-68 conflict-free.
// ---------------------------------------------------------------------------
#define GU_ST    14848
#define GU_SMEM  (1024 + 6 * GU_ST)

__global__ __launch_bounds__(256) void k_gateup(const float* __restrict__ Wg,
                                                const float* __restrict__ Wu) {
    extern __shared__ char smem[];
    int e = blockIdx.y;
    int n = g_cnt[e];
    if (n == 0) return;
    int f0 = blockIdx.x * 64;
    uint32_t sb = smem_u32(smem);
    int tid = threadIdx.x, lane = tid & 31, warp = tid >> 5;
    int wm = warp >> 1, wn = warp & 1;
    int lq = lane >> 2, lr = lane & 3;
    int* toks = (int*)smem;
    const float* wg = Wg + (size_t)e * HD * FF + f0;
    const float* wu = Wu + (size_t)e * HD * FF + f0;

    int ar = tid >> 1, ac = tid & 1;           // A: row, 16B chunk (8 halves)
    int bkk = tid >> 4, bcc = tid & 15;        // B: k-row, 16B chunk

    for (int s0 = 0; s0 < n; s0 += 128) {
        __syncthreads();
        int nt = min(128, n - s0);
        if (tid < 128) toks[tid] = g_tok[e * TT + s0 + ((tid < nt) ? tid : 0)];
        __syncthreads();
        const __half* xrow = g_xh + (size_t)toks[ar] * HD;

#pragma unroll
        for (int s = 0; s < 5; s++) {
            uint32_t st = sb + 1024 + s * GU_ST;
            cp16(st + ar * 48 + ac * 16, xrow + s * 16 + ac * 8);
            cp16(st + 6144 + bkk * 272 + bcc * 16, wg + (size_t)(s * 16 + bkk) * FF + bcc * 4);
            cp16(st + 10496 + bkk * 272 + bcc * 16, wu + (size_t)(s * 16 + bkk) * FF + bcc * 4);
            CP_COMMIT();
        }

        float accg[2][4][4] = {}, accu[2][4][4] = {};

        int cur = 0;
        for (int i = 0; i < 128; i++) {
            CP_WAIT4();
            __syncthreads();
            int nx = i + 5;
            if (nx < 128) {
                int nst = nx - 5 * ((nx * 0x5556) >> 16);   // nx % 6 via mul? keep simple:
                nst = nx % 6;
                uint32_t st = sb + 1024 + nst * GU_ST;
                int kn = nx * 16;
                cp16(st + ar * 48 + ac * 16, xrow + kn + ac * 8);
                cp16(st + 6144 + bkk * 272 + bcc * 16, wg + (size_t)(kn + bkk) * FF + bcc * 4);
                cp16(st + 10496 + bkk * 272 + bcc * 16, wu + (size_t)(kn + bkk) * FF + bcc * 4);
            }
            CP_COMMIT();

            const char* stg = smem + 1024 + cur * GU_ST;
            const unsigned* Aw = (const unsigned*)stg;
            const float* Bg = (const float*)(stg + 6144);
            const float* Bu = (const float*)(stg + 10496);

            unsigned a[2][4];
#pragma unroll
            for (int mi = 0; mi < 2; mi++) {
                int r = wm * 32 + mi * 16 + lq;
                a[mi][0] = Aw[r * 12 + lr];
                a[mi][1] = Aw[(r + 8) * 12 + lr];
                a[mi][2] = Aw[r * 12 + lr + 4];
                a[mi][3] = Aw[(r + 8) * 12 + lr + 4];
            }
#pragma unroll
            for (int ni = 0; ni < 4; ni++) {
                int nn = wn * 32 + ni * 8 + lq;
                unsigned g0 = pack_h2(Bg[(2 * lr) * 68 + nn],     Bg[(2 * lr + 1) * 68 + nn]);
                unsigned g1 = pack_h2(Bg[(2 * lr + 8) * 68 + nn], Bg[(2 * lr + 9) * 68 + nn]);
                unsigned u0 = pack_h2(Bu[(2 * lr) * 68 + nn],     Bu[(2 * lr + 1) * 68 + nn]);
                unsigned u1 = pack_h2(Bu[(2 * lr + 8) * 68 + nn], Bu[(2 * lr + 9) * 68 + nn]);
#pragma unroll
                for (int mi = 0; mi < 2; mi++) {
                    mma_f16(accg[mi][ni][0], accg[mi][ni][1], accg[mi][ni][2], accg[mi][ni][3],
                            a[mi][0], a[mi][1], a[mi][2], a[mi][3], g0, g1);
                    mma_f16(accu[mi][ni][0], accu[mi][ni][1], accu[mi][ni][2], accu[mi][ni][3],
                            a[mi][0], a[mi][1], a[mi][2], a[mi][3], u0, u1);
                }
            }
            if (++cur == 6) cur = 0;
        }

        // epilogue: SwiGLU * comb -> g_acth (fp16)
#pragma unroll
        for (int mi = 0; mi < 2; mi++)
#pragma unroll
            for (int half = 0; half < 2; half++) {
                int r = wm * 32 + mi * 16 + lq + half * 8;
                if (r < nt) {
                    float wc = g_wgt[e * TT + s0 + r];
                    size_t base = ((size_t)e * TT + s0 + r) * FF + f0 + wn * 32;
#pragma unroll
                    for (int ni = 0; ni < 4; ni++) {
                        float av[2];
#pragma unroll
                        for (int c = 0; c < 2; c++) {
                            float gv = accg[mi][ni][half * 2 + c];
                            float uv = accu[mi][ni][half * 2 + c];
                            av[c] = gv / (1.0f + expf(-gv)) * uv * wc;
                        }
                        *(unsigned*)&g_acth[base + ni * 8 + lr * 2] = pack_h2(av[0], av[1]);
                    }
                }
            }
    }
}

// ---------------------------------------------------------------------------
// K4: down projection, 6-stage cp.async pipeline, fp16 mma. A from g_acth.
// M=128 x N=64, K=FF. grid (HD/64, EE).
// Stage (10496 B): A fp16 [128][12w] (6144 B) | B f32 [16][68w] (4352 B)
// ---------------------------------------------------------------------------
#define DN_ST    10496
#define DN_SMEM  (1024 + 6 * DN_ST)

__global__ __launch_bounds__(256) void k_down(const float* __restrict__ Wd,
                                              float* __restrict__ out) {
    extern __shared__ char smem[];
    int e = blockIdx.y;
    int n = g_cnt[e];
    if (n == 0) return;
    int h0 = blockIdx.x * 64;
    uint32_t sb = smem_u32(smem);
    int tid = threadIdx.x, lane = tid & 31, warp = tid >> 5;
    int wm = warp >> 1, wn = warp & 1;
    int lq = lane >> 2, lr = lane & 3;
    int* toks = (int*)smem;
    const float* wd = Wd + (size_t)e * FF * HD + h0;

    int ar = tid >> 1, ac = tid & 1;
    int bkk = tid >> 4, bcc = tid & 15;

    for (int s0 = 0; s0 < n; s0 += 128) {
        __syncthreads();
        int nt = min(128, n - s0);
        if (tid < 128) toks[tid] = g_tok[e * TT + s0 + ((tid < nt) ? tid : 0)];
        __syncthreads();

        const __half* arow = g_acth + ((size_t)e * TT + s0 + ((ar < nt) ? ar : 0)) * FF;

#pragma unroll
        for (int s = 0; s < 5; s++) {
            uint32_t st = sb + 1024 + s * DN_ST;
            cp16(st + ar * 48 + ac * 16, arow + s * 16 + ac * 8);
            cp16(st + 6144 + bkk * 272 + bcc * 16, wd + (size_t)(s * 16 + bkk) * HD + bcc * 4);
            CP_COMMIT();
        }

        float acc[2][4][4] = {};

        int cur = 0;
        for (int i = 0; i < 64; i++) {
            CP_WAIT4();
            __syncthreads();
            int nx = i + 5;
            if (nx < 64) {
                int nst = nx % 6;
                uint32_t st = sb + 1024 + nst * DN_ST;
                int kn = nx * 16;
                cp16(st + ar * 48 + ac * 16, arow + kn + ac * 8);
                cp16(st + 6144 + bkk * 272 + bcc * 16, wd + (size_t)(kn + bkk) * HD + bcc * 4);
            }
            CP_COMMIT();

            const char* stg = smem + 1024 + cur * DN_ST;
            const unsigned* Aw = (const unsigned*)stg;
            const float* B = (const float*)(stg + 6144);

            unsigned a[2][4];
#pragma unroll
            for (int mi = 0; mi < 2; mi++) {
                int r = wm * 32 + mi * 16 + lq;
                a[mi][0] = Aw[r * 12 + lr];
                a[mi][1] = Aw[(r + 8) * 12 + lr];
                a[mi][2] = Aw[r * 12 + lr + 4];
                a[mi][3] = Aw[(r + 8) * 12 + lr + 4];
            }
#pragma unroll
            for (int ni = 0; ni < 4; ni++) {
                int nn = wn * 32 + ni * 8 + lq;
                unsigned b0 = pack_h2(B[(2 * lr) * 68 + nn],     B[(2 * lr + 1) * 68 + nn]);
                unsigned b1 = pack_h2(B[(2 * lr + 8) * 68 + nn], B[(2 * lr + 9) * 68 + nn]);
#pragma unroll
                for (int mi = 0; mi < 2; mi++)
                    mma_f16(acc[mi][ni][0], acc[mi][ni][1], acc[mi][ni][2], acc[mi][ni][3],
                            a[mi][0], a[mi][1], a[mi][2], a[mi][3], b0, b1);
            }
            if (++cur == 6) cur = 0;
        }

        // epilogue: atomicAdd into out
#pragma unroll
        for (int mi = 0; mi < 2; mi++)
#pragma unroll
            for (int half = 0; half < 2; half++) {
                int r = wm * 32 + mi * 16 + lq + half * 8;
                if (r < nt) {
                    int t = toks[r];
                    size_t base = (size_t)t * HD + h0 + wn * 32;
#pragma unroll
                    for (int ni = 0; ni < 4; ni++)
#pragma unroll
                        for (int c = 0; c < 2; c++)
                            atomicAdd(&out[base + ni * 8 + lr * 2 + c],
                                      acc[mi][ni][half * 2 + c]);
                }
            }
    }
}

// ---------------------------------------------------------------------------
// launch
// ---------------------------------------------------------------------------
extern "C" void kernel_launch(void* const* d_in, const int* in_sizes, int n_in,
                              void* d_out, int out_size) {
    const float* x      = (const float*)d_in[0];
    const float* u      = (const float*)d_in[1];
    const float* gate_w = (const float*)d_in[2];
    const float* z_w1   = (const float*)d_in[3];
    const float* z_b1   = (const float*)d_in[4];
    const float* z_w2   = (const float*)d_in[5];
    const float* z_b2   = (const float*)d_in[6];
    const float* Umat   = (const float*)d_in[7];
    const float* Wg     = (const float*)d_in[8];
    const float* Wu     = (const float*)d_in[9];
    const float* Wd     = (const float*)d_in[10];
    float* out = (float*)d_out;

    cudaFuncSetAttribute(k_gateup, cudaFuncAttributeMaxDynamicSharedMemorySize, GU_SMEM);
    cudaFuncSetAttribute(k_down,   cudaFuncAttributeMaxDynamicSharedMemorySize, DN_SMEM);

    k_zero<<<(TT * HD + 255) / 256, 256>>>(out, x);
    k_zh<<<dim3(ZHD / 64, TT / 128), 256>>>(x, z_w1, z_b1);
    k_router<<<TT, 128>>>(x, u, gate_w, z_w2, z_b2, Umat);
    k_gateup<<<dim3(FF / 64, EE), 256, GU_SMEM>>>(Wg, Wu);
    k_down<<<dim3(HD / 64, EE), 256, DN_SMEM>>>(Wd, out);
}